// round 13
// baseline (speedup 1.0000x reference)
#include <cuda_runtime.h>
#include <cuda_fp16.h>
#include <math.h>
#include <stdint.h>

#define HID 128
#define MAX_N 100000
#define MAX_E 600000
#define SCAN_BS 256

// Scratch (device globals: zero-initialized at module load; every launch
// restores them to zero -> graph-replay deterministic)
__device__ __align__(16) __half g_h2[MAX_N * HID];   // fp16(dinv[r] * relu(x)@W)
__device__ __align__(16) __half g_agg2[MAX_N * HID]; // fp16 aggregated messages
__device__ int   g_deg[MAX_N];
__device__ int   g_off[MAX_N];
__device__ int   g_cursor[MAX_N];
__device__ int   g_bsrc[MAX_E];
__device__ int   g_total;
__device__ float g_dinv[MAX_N];
__device__ __align__(16) float g_colsum[HID];
__device__ __align__(16) float g_colsq[HID];

// ---------------------------------------------------------------------------
// 1) in-degree from targets (edge_index is int32). g_deg zeroed by prior
//    launch's kk_aggstats (or module load).
__global__ void kk_deg(const int* __restrict__ col, int e) {
    int i = blockIdx.x * blockDim.x + threadIdx.x;
    if (i < e) atomicAdd(&g_deg[col[i]], 1);
}

// 2) single-pass offset allocation: block-local scan + atomic bump base.
//    Also computes dinv and zeroes the BN column accumulators (block 0).
__global__ void kk_allocscan(int n) {
    __shared__ int sd[SCAN_BS];
    __shared__ int sbase;
    int t = threadIdx.x;
    int idx = blockIdx.x * SCAN_BS + t;
    if (blockIdx.x == 0 && t < HID) { g_colsum[t] = 0.f; g_colsq[t] = 0.f; }
    int v = (idx < n) ? g_deg[idx] : 0;
    if (idx < n) g_dinv[idx] = rsqrtf((float)(v + 1));
    sd[t] = v;
    __syncthreads();
    #pragma unroll
    for (int s = 1; s < SCAN_BS; s <<= 1) {
        int x = (t >= s) ? sd[t - s] : 0;
        __syncthreads();
        sd[t] += x;
        __syncthreads();
    }
    if (t == SCAN_BS - 1) sbase = atomicAdd(&g_total, sd[t]);
    __syncthreads();
    if (idx < n) g_off[idx] = sbase + sd[t] - v;
}

// 3) scatter edges into destination buckets
__global__ void kk_scatter(const int* __restrict__ rows,
                           const int* __restrict__ cols, int e) {
    int i = blockIdx.x * blockDim.x + threadIdx.x;
    if (i >= e) return;
    int c = cols[i];
    int p = atomicAdd(&g_cursor[c], 1);
    g_bsrc[g_off[c] + p] = rows[i];
}

// ---------------------------------------------------------------------------
// 4) h2 = fp16(dinv * (relu(x) @ W)) via fp16 mma.sync m16n8k16, B-stationary.
//    128 threads (4 warps). Warp w owns COLUMN strip w*32..w*32+31.
#define HROW 272                         // bytes per smem row (128*2 + 16 pad)
#define SM_TOT (128 * HROW)              // 34816 B (W staging; reused for x)

__global__ void __launch_bounds__(128, 3)
kk_gemm(const float* __restrict__ x, const float* __restrict__ W, int n) {
    extern __shared__ char sm[];
    int t = threadIdx.x;
    int w = t >> 5, lane = t & 31;
    int qr = lane >> 2;          // 0..7
    int qc = lane & 3;           // 0..3

    // stage W^T as fp16: sm[nn][k] = h(W[k*128 + nn])
    for (int k = 0; k < HID; k++)
        *(__half*)(sm + t * HROW + k * 2) = __float2half_rn(W[k * HID + t]);
    __syncthreads();

    // hoist B fragments: n = w*32 + nb*8 + qr, k = kk*16 + qc*2 (+8)
    uint32_t bf[8][4][2];
    #pragma unroll
    for (int kk = 0; kk < 8; kk++)
        #pragma unroll
        for (int nb = 0; nb < 4; nb++) {
            const char* p = sm + (w * 32 + nb * 8 + qr) * HROW + kk * 32 + qc * 4;
            bf[kk][nb][0] = *(const uint32_t*)p;
            bf[kk][nb][1] = *(const uint32_t*)(p + 16);
        }
    __syncthreads();   // W staging dead; reuse rows 0..31 for x tile

    for (int row0 = blockIdx.x * 32; row0 < n; row0 += gridDim.x * 32) {
        int rmax = min(32, n - row0);
        // load 32x128 x tile -> fp16 smem with ReLU (4 iters x 8 cols/thread)
        #pragma unroll
        for (int it = 0; it < 4; it++) {
            int idx = t + it * 128;           // 0..511
            int r = idx >> 4, c8 = idx & 15;
            uint4 pk;
            if (r < rmax) {
                const float4* src =
                    (const float4*)&x[(size_t)(row0 + r) * HID + c8 * 8];
                float4 a = src[0], b = src[1];
                __half2 h0 = __floats2half2_rn(fmaxf(a.x, 0.f), fmaxf(a.y, 0.f));
                __half2 h1 = __floats2half2_rn(fmaxf(a.z, 0.f), fmaxf(a.w, 0.f));
                __half2 h2 = __floats2half2_rn(fmaxf(b.x, 0.f), fmaxf(b.y, 0.f));
                __half2 h3 = __floats2half2_rn(fmaxf(b.z, 0.f), fmaxf(b.w, 0.f));
                pk = make_uint4(*(uint32_t*)&h0, *(uint32_t*)&h1,
                                *(uint32_t*)&h2, *(uint32_t*)&h3);
            } else {
                pk = make_uint4(0, 0, 0, 0);
            }
            *(uint4*)(sm + r * HROW + c8 * 16) = pk;  // 272 = 17*16, aligned
        }
        __syncthreads();

        float acc[2][4][4];
        #pragma unroll
        for (int rg = 0; rg < 2; rg++)
            #pragma unroll
            for (int nb = 0; nb < 4; nb++)
                #pragma unroll
                for (int j = 0; j < 4; j++) acc[rg][nb][j] = 0.f;

        #pragma unroll
        for (int kk = 0; kk < 8; kk++) {
            #pragma unroll
            for (int rg = 0; rg < 2; rg++) {
                const char* pA = sm + (rg * 16 + qr) * HROW + kk * 32 + qc * 4;
                uint32_t a0 = *(const uint32_t*)(pA);
                uint32_t a1 = *(const uint32_t*)(pA + 8 * HROW);
                uint32_t a2 = *(const uint32_t*)(pA + 16);
                uint32_t a3 = *(const uint32_t*)(pA + 8 * HROW + 16);
                #pragma unroll
                for (int nb = 0; nb < 4; nb++) {
                    asm volatile(
                        "mma.sync.aligned.m16n8k16.row.col.f32.f16.f16.f32 "
                        "{%0,%1,%2,%3}, {%4,%5,%6,%7}, {%8,%9}, {%0,%1,%2,%3};"
                        : "+f"(acc[rg][nb][0]), "+f"(acc[rg][nb][1]),
                          "+f"(acc[rg][nb][2]), "+f"(acc[rg][nb][3])
                        : "r"(a0), "r"(a1), "r"(a2), "r"(a3),
                          "r"(bf[kk][nb][0]), "r"(bf[kk][nb][1]));
                }
            }
        }

        // epilogue: h2[row] = fp16(dinv[row] * acc)
        #pragma unroll
        for (int rg = 0; rg < 2; rg++) {
            int r_lo = row0 + rg * 16 + qr;
            int r_hi = r_lo + 8;
            float d_lo = (r_lo < n) ? g_dinv[r_lo] : 0.f;
            float d_hi = (r_hi < n) ? g_dinv[r_hi] : 0.f;
            #pragma unroll
            for (int nb = 0; nb < 4; nb++) {
                int c = w * 32 + nb * 8 + qc * 2;
                if (r_lo < n) {
                    __half2 hv = __floats2half2_rn(acc[rg][nb][0] * d_lo,
                                                   acc[rg][nb][1] * d_lo);
                    *(__half2*)&g_h2[(size_t)r_lo * HID + c] = hv;
                }
                if (r_hi < n) {
                    __half2 hv = __floats2half2_rn(acc[rg][nb][2] * d_hi,
                                                   acc[rg][nb][3] * d_hi);
                    *(__half2*)&g_h2[(size_t)r_hi * HID + c] = hv;
                }
            }
        }
        __syncthreads();
    }
}

// ---------------------------------------------------------------------------
// 5) destination-gather aggregation + fused BN stats (one warp per node).
//    agg[c] = dinv[c] * ( sum_src h2[src] + h2[c] ); stored fp16.
//    Stats accumulated from fp32 (pre-quantization). Also resets deg/cursor.
__global__ void __launch_bounds__(256)
kk_aggstats(int n) {
    __shared__ float bsum[HID], bsq[HID];
    int t = threadIdx.x;
    int lane = t & 31;
    int w = t >> 5;
    if (t < HID) { bsum[t] = 0.f; bsq[t] = 0.f; }
    __syncthreads();

    int warp_id = blockIdx.x * 8 + w;
    int nwarps = gridDim.x * 8;

    float4 csum = make_float4(0.f, 0.f, 0.f, 0.f);
    float4 csq  = make_float4(0.f, 0.f, 0.f, 0.f);

    for (int node = warp_id; node < n; node += nwarps) {
        int start = g_off[node];
        int cnt   = g_deg[node];
        float dd  = g_dinv[node];
        if (lane == 0) { g_deg[node] = 0; g_cursor[node] = 0; }  // state reset

        uint2 sv = ((const uint2*)(g_h2 + (size_t)node * HID))[lane];
        float2 f0 = __half22float2(*(__half2*)&sv.x);
        float2 f1 = __half22float2(*(__half2*)&sv.y);
        float4 acc = make_float4(f0.x, f0.y, f1.x, f1.y);  // self: h2[c]

        int j = 0;
        for (; j + 2 <= cnt; j += 2) {
            int s0 = g_bsrc[start + j];
            int s1 = g_bsrc[start + j + 1];
            uint2 a = ((const uint2*)(g_h2 + (size_t)s0 * HID))[lane];
            uint2 b = ((const uint2*)(g_h2 + (size_t)s1 * HID))[lane];
            float2 a0 = __half22float2(*(__half2*)&a.x);
            float2 a1 = __half22float2(*(__half2*)&a.y);
            float2 b0 = __half22float2(*(__half2*)&b.x);
            float2 b1 = __half22float2(*(__half2*)&b.y);
            acc.x += a0.x + b0.x;
            acc.y += a0.y + b0.y;
            acc.z += a1.x + b1.x;
            acc.w += a1.y + b1.y;
        }
        if (j < cnt) {
            int s0 = g_bsrc[start + j];
            uint2 a = ((const uint2*)(g_h2 + (size_t)s0 * HID))[lane];
            float2 a0 = __half22float2(*(__half2*)&a.x);
            float2 a1 = __half22float2(*(__half2*)&a.y);
            acc.x += a0.x; acc.y += a0.y;
            acc.z += a1.x; acc.w += a1.y;
        }

        float4 agg4 = make_float4(dd * acc.x, dd * acc.y, dd * acc.z, dd * acc.w);
        __half2 p0 = __floats2half2_rn(agg4.x, agg4.y);
        __half2 p1 = __floats2half2_rn(agg4.z, agg4.w);
        ((uint2*)(g_agg2 + (size_t)node * HID))[lane] =
            make_uint2(*(uint32_t*)&p0, *(uint32_t*)&p1);

        csum.x += agg4.x; csum.y += agg4.y; csum.z += agg4.z; csum.w += agg4.w;
        csq.x += agg4.x * agg4.x; csq.y += agg4.y * agg4.y;
        csq.z += agg4.z * agg4.z; csq.w += agg4.w * agg4.w;
    }

    atomicAdd(&bsum[lane * 4 + 0], csum.x);
    atomicAdd(&bsum[lane * 4 + 1], csum.y);
    atomicAdd(&bsum[lane * 4 + 2], csum.z);
    atomicAdd(&bsum[lane * 4 + 3], csum.w);
    atomicAdd(&bsq[lane * 4 + 0], csq.x);
    atomicAdd(&bsq[lane * 4 + 1], csq.y);
    atomicAdd(&bsq[lane * 4 + 2], csq.z);
    atomicAdd(&bsq[lane * 4 + 3], csq.w);
    __syncthreads();
    if (t < HID) {
        atomicAdd(&g_colsum[t], bsum[t]);
        atomicAdd(&g_colsq[t], bsq[t]);
    }
}

// 6) out = scale[c]*agg + shift[c]; BN coefficients per block; resets g_total.
__global__ void __launch_bounds__(256)
kk_out(float* __restrict__ out, const float* __restrict__ gamma,
       const float* __restrict__ beta, float inv_n, int n) {
    __shared__ float ssc[HID], ssh[HID];
    int t = threadIdx.x;
    if (blockIdx.x == 0 && t == 0) g_total = 0;   // state reset for next call
    if (t < HID) {
        float mean = g_colsum[t] * inv_n;
        float var = g_colsq[t] * inv_n - mean * mean;
        float sc = gamma[t] * rsqrtf(var + 1e-5f);
        ssc[t] = sc;
        ssh[t] = beta[t] - sc * mean;
    }
    __syncthreads();

    size_t total = (size_t)n * 32;   // groups of 4 cols
    for (size_t i = (size_t)blockIdx.x * blockDim.x + t; i < total;
         i += (size_t)gridDim.x * blockDim.x) {
        int c4 = (int)(i & 31);
        uint2 a = ((const uint2*)g_agg2)[i];
        float2 a0 = __half22float2(*(__half2*)&a.x);
        float2 a1 = __half22float2(*(__half2*)&a.y);
        float4 sc = *(const float4*)&ssc[c4 * 4];
        float4 sh = *(const float4*)&ssh[c4 * 4];
        float4 v;
        v.x = fmaf(a0.x, sc.x, sh.x);
        v.y = fmaf(a0.y, sc.y, sh.y);
        v.z = fmaf(a1.x, sc.z, sh.z);
        v.w = fmaf(a1.y, sc.w, sh.w);
        ((float4*)out)[i] = v;
    }
}

// ---------------------------------------------------------------------------
extern "C" void kernel_launch(void* const* d_in, const int* in_sizes, int n_in,
                              void* d_out, int out_size) {
    const float* x = (const float*)d_in[0];
    const int* ei = (const int*)d_in[1];          // int32 (JAX x64 disabled)
    const float* W = (const float*)d_in[2];
    const float* gamma = (const float*)d_in[4];
    const float* beta = (const float*)d_in[5];
    float* out = (float*)d_out;

    int n = in_sizes[0] / HID;
    int e = in_sizes[1] / 2;
    const int* erow = ei;
    const int* ecol = ei + e;

    int nb = (n + SCAN_BS - 1) / SCAN_BS;

    kk_deg<<<(e + 255) / 256, 256>>>(ecol, e);
    kk_allocscan<<<nb, SCAN_BS>>>(n);
    kk_scatter<<<(e + 255) / 256, 256>>>(erow, ecol, e);

    {
        cudaFuncSetAttribute(kk_gemm, cudaFuncAttributeMaxDynamicSharedMemorySize,
                             SM_TOT);
        int need = (n + 31) / 32;
        int blocks = need < 444 ? need : 444;  // persistent, 3 CTAs/SM
        kk_gemm<<<blocks, 128, SM_TOT>>>(x, W, n);
    }

    kk_aggstats<<<1184, 256>>>(n);
    kk_out<<<2048, 256>>>(out, gamma, beta, 1.0f / (float)n, n);
}

// round 15
// speedup vs baseline: 1.1651x; 1.1651x over previous
#include <cuda_runtime.h>
#include <cuda_fp16.h>
#include <math.h>
#include <stdint.h>

#define HID 128
#define MAX_N 100000
#define MAX_E 600000
#define SCAN_BS 256

// Scratch (device globals: zero-initialized at module load; every launch
// restores them to zero -> graph-replay deterministic)
__device__ __align__(16) __half g_h2[MAX_N * HID];   // fp16(dinv[r] * relu(x)@W)
__device__ __align__(16) __half g_agg2[MAX_N * HID]; // fp16 aggregated messages
__device__ int   g_deg[MAX_N];
__device__ int   g_off[MAX_N];
__device__ int   g_cursor[MAX_N];
__device__ int   g_bsrc[MAX_E];
__device__ int   g_total;
__device__ float g_dinv[MAX_N];
__device__ __align__(16) float g_colsum[HID];
__device__ __align__(16) float g_colsq[HID];

// ---------------------------------------------------------------------------
// 1) in-degree from targets (edge_index is int32). g_deg zeroed by prior
//    launch's kk_aggstats (or module load).
__global__ void kk_deg(const int* __restrict__ col, int e) {
    int i = blockIdx.x * blockDim.x + threadIdx.x;
    if (i < e) atomicAdd(&g_deg[col[i]], 1);
}

// 2) single-pass offset allocation: block-local scan + atomic bump base.
//    Also computes dinv and zeroes the BN column accumulators (block 0).
__global__ void kk_allocscan(int n) {
    __shared__ int sd[SCAN_BS];
    __shared__ int sbase;
    int t = threadIdx.x;
    int idx = blockIdx.x * SCAN_BS + t;
    if (blockIdx.x == 0 && t < HID) { g_colsum[t] = 0.f; g_colsq[t] = 0.f; }
    int v = (idx < n) ? g_deg[idx] : 0;
    if (idx < n) g_dinv[idx] = rsqrtf((float)(v + 1));
    sd[t] = v;
    __syncthreads();
    #pragma unroll
    for (int s = 1; s < SCAN_BS; s <<= 1) {
        int x = (t >= s) ? sd[t - s] : 0;
        __syncthreads();
        sd[t] += x;
        __syncthreads();
    }
    if (t == SCAN_BS - 1) sbase = atomicAdd(&g_total, sd[t]);
    __syncthreads();
    if (idx < n) g_off[idx] = sbase + sd[t] - v;
}

// 3) scatter edges into destination buckets
__global__ void kk_scatter(const int* __restrict__ rows,
                           const int* __restrict__ cols, int e) {
    int i = blockIdx.x * blockDim.x + threadIdx.x;
    if (i >= e) return;
    int c = cols[i];
    int p = atomicAdd(&g_cursor[c], 1);
    g_bsrc[g_off[c] + p] = rows[i];
}

// ---------------------------------------------------------------------------
// 4) h2 = fp16(dinv * (relu(x) @ W)) via fp16 mma.sync m16n8k16, B-stationary,
//    software-pipelined (double-buffered x tile, prefetch LDG before MMA).
//    128 threads (4 warps). Warp w owns COLUMN strip w*32..w*32+31.
//    Tile-slot mapping: it2 = 0..3, idx = t + it2*128 (0..511),
//    r = idx>>4 (0..31), c8 = idx&15; slot holds 8 floats -> pf[2*it2 .. +1].
#define HROW 272                         // bytes per smem row (128*2 + 16 pad)
#define TILE_B (32 * HROW)               // one x-tile buffer = 8704 B
#define SM_TOT (128 * HROW)              // 34816 B (W staging; then 2 buffers)

__global__ void __launch_bounds__(128, 3)
kk_gemm(const float* __restrict__ x, const float* __restrict__ W, int n) {
    extern __shared__ char sm[];
    int t = threadIdx.x;
    int w = t >> 5, lane = t & 31;
    int qr = lane >> 2;          // 0..7
    int qc = lane & 3;           // 0..3

    // stage W^T as fp16: sm[nn][k] = h(W[k*128 + nn])
    for (int k = 0; k < HID; k++)
        *(__half*)(sm + t * HROW + k * 2) = __float2half_rn(W[k * HID + t]);
    __syncthreads();

    // hoist B fragments: n = w*32 + nb*8 + qr, k = kk*16 + qc*2 (+8)
    uint32_t bf[8][4][2];
    #pragma unroll
    for (int kk = 0; kk < 8; kk++)
        #pragma unroll
        for (int nb = 0; nb < 4; nb++) {
            const char* p = sm + (w * 32 + nb * 8 + qr) * HROW + kk * 32 + qc * 4;
            bf[kk][nb][0] = *(const uint32_t*)p;
            bf[kk][nb][1] = *(const uint32_t*)(p + 16);
        }
    __syncthreads();   // W staging dead; sm reused as two x-tile buffers

    int step = gridDim.x * 32;
    int row0 = blockIdx.x * 32;
    if (row0 >= n) return;

    float4 pf[8];
    // initial tile load into regs
    #pragma unroll
    for (int it2 = 0; it2 < 4; it2++) {
        int idx = t + it2 * 128;          // 0..511
        int r = idx >> 4, c8 = idx & 15;
        if (row0 + r < n) {
            const float4* src = (const float4*)&x[(size_t)(row0 + r) * HID + c8 * 8];
            pf[2 * it2] = src[0];
            pf[2 * it2 + 1] = src[1];
        } else {
            pf[2 * it2] = make_float4(0.f, 0.f, 0.f, 0.f);
            pf[2 * it2 + 1] = make_float4(0.f, 0.f, 0.f, 0.f);
        }
    }
    // convert + STS into buf0
    #pragma unroll
    for (int it2 = 0; it2 < 4; it2++) {
        int idx = t + it2 * 128;
        int r = idx >> 4, c8 = idx & 15;
        float4 a = pf[2 * it2], b = pf[2 * it2 + 1];
        __half2 h0 = __floats2half2_rn(fmaxf(a.x, 0.f), fmaxf(a.y, 0.f));
        __half2 h1 = __floats2half2_rn(fmaxf(a.z, 0.f), fmaxf(a.w, 0.f));
        __half2 h2 = __floats2half2_rn(fmaxf(b.x, 0.f), fmaxf(b.y, 0.f));
        __half2 h3 = __floats2half2_rn(fmaxf(b.z, 0.f), fmaxf(b.w, 0.f));
        *(uint4*)(sm + r * HROW + c8 * 16) =
            make_uint4(*(uint32_t*)&h0, *(uint32_t*)&h1,
                       *(uint32_t*)&h2, *(uint32_t*)&h3);
    }
    __syncthreads();

    int buf = 0;
    while (true) {
        int row1 = row0 + step;
        // prefetch next tile (LDG issued before MMA; latency overlapped)
        if (row1 < n) {
            #pragma unroll
            for (int it2 = 0; it2 < 4; it2++) {
                int idx = t + it2 * 128;
                int r = idx >> 4, c8 = idx & 15;
                if (row1 + r < n) {
                    const float4* src =
                        (const float4*)&x[(size_t)(row1 + r) * HID + c8 * 8];
                    pf[2 * it2] = src[0];
                    pf[2 * it2 + 1] = src[1];
                } else {
                    pf[2 * it2] = make_float4(0.f, 0.f, 0.f, 0.f);
                    pf[2 * it2 + 1] = make_float4(0.f, 0.f, 0.f, 0.f);
                }
            }
        }

        // MMA on current buffer
        char* cbuf = sm + buf * TILE_B;
        float acc[2][4][4];
        #pragma unroll
        for (int rg = 0; rg < 2; rg++)
            #pragma unroll
            for (int nb = 0; nb < 4; nb++)
                #pragma unroll
                for (int j = 0; j < 4; j++) acc[rg][nb][j] = 0.f;

        #pragma unroll
        for (int kk = 0; kk < 8; kk++) {
            #pragma unroll
            for (int rg = 0; rg < 2; rg++) {
                const char* pA = cbuf + (rg * 16 + qr) * HROW + kk * 32 + qc * 4;
                uint32_t a0 = *(const uint32_t*)(pA);
                uint32_t a1 = *(const uint32_t*)(pA + 8 * HROW);
                uint32_t a2 = *(const uint32_t*)(pA + 16);
                uint32_t a3 = *(const uint32_t*)(pA + 8 * HROW + 16);
                #pragma unroll
                for (int nb = 0; nb < 4; nb++) {
                    asm volatile(
                        "mma.sync.aligned.m16n8k16.row.col.f32.f16.f16.f32 "
                        "{%0,%1,%2,%3}, {%4,%5,%6,%7}, {%8,%9}, {%0,%1,%2,%3};"
                        : "+f"(acc[rg][nb][0]), "+f"(acc[rg][nb][1]),
                          "+f"(acc[rg][nb][2]), "+f"(acc[rg][nb][3])
                        : "r"(a0), "r"(a1), "r"(a2), "r"(a3),
                          "r"(bf[kk][nb][0]), "r"(bf[kk][nb][1]));
                }
            }
        }

        // epilogue: h2[row] = fp16(dinv[row] * acc)
        #pragma unroll
        for (int rg = 0; rg < 2; rg++) {
            int r_lo = row0 + rg * 16 + qr;
            int r_hi = r_lo + 8;
            float d_lo = (r_lo < n) ? g_dinv[r_lo] : 0.f;
            float d_hi = (r_hi < n) ? g_dinv[r_hi] : 0.f;
            #pragma unroll
            for (int nb = 0; nb < 4; nb++) {
                int c = w * 32 + nb * 8 + qc * 2;
                if (r_lo < n) {
                    __half2 hv = __floats2half2_rn(acc[rg][nb][0] * d_lo,
                                                   acc[rg][nb][1] * d_lo);
                    *(__half2*)&g_h2[(size_t)r_lo * HID + c] = hv;
                }
                if (r_hi < n) {
                    __half2 hv = __floats2half2_rn(acc[rg][nb][2] * d_hi,
                                                   acc[rg][nb][3] * d_hi);
                    *(__half2*)&g_h2[(size_t)r_hi * HID + c] = hv;
                }
            }
        }

        if (row1 >= n) break;

        // convert prefetched regs + STS into other buffer
        char* nbuf = sm + (buf ^ 1) * TILE_B;
        #pragma unroll
        for (int it2 = 0; it2 < 4; it2++) {
            int idx = t + it2 * 128;
            int r = idx >> 4, c8 = idx & 15;
            float4 a = pf[2 * it2], b = pf[2 * it2 + 1];
            __half2 h0 = __floats2half2_rn(fmaxf(a.x, 0.f), fmaxf(a.y, 0.f));
            __half2 h1 = __floats2half2_rn(fmaxf(a.z, 0.f), fmaxf(a.w, 0.f));
            __half2 h2 = __floats2half2_rn(fmaxf(b.x, 0.f), fmaxf(b.y, 0.f));
            __half2 h3 = __floats2half2_rn(fmaxf(b.z, 0.f), fmaxf(b.w, 0.f));
            *(uint4*)(nbuf + r * HROW + c8 * 16) =
                make_uint4(*(uint32_t*)&h0, *(uint32_t*)&h1,
                           *(uint32_t*)&h2, *(uint32_t*)&h3);
        }
        __syncthreads();
        buf ^= 1;
        row0 = row1;
    }
}

// ---------------------------------------------------------------------------
// 5) destination-gather aggregation + fused BN stats (one warp per node).
//    agg[c] = dinv[c] * ( sum_src h2[src] + h2[c] ); stored fp16.
__global__ void __launch_bounds__(256)
kk_aggstats(int n) {
    __shared__ float bsum[HID], bsq[HID];
    int t = threadIdx.x;
    int lane = t & 31;
    int w = t >> 5;
    if (t < HID) { bsum[t] = 0.f; bsq[t] = 0.f; }
    __syncthreads();

    int warp_id = blockIdx.x * 8 + w;
    int nwarps = gridDim.x * 8;

    float4 csum = make_float4(0.f, 0.f, 0.f, 0.f);
    float4 csq  = make_float4(0.f, 0.f, 0.f, 0.f);

    for (int node = warp_id; node < n; node += nwarps) {
        int start = g_off[node];
        int cnt   = g_deg[node];
        float dd  = g_dinv[node];
        if (lane == 0) { g_deg[node] = 0; g_cursor[node] = 0; }  // state reset

        uint2 sv = ((const uint2*)(g_h2 + (size_t)node * HID))[lane];
        float2 f0 = __half22float2(*(__half2*)&sv.x);
        float2 f1 = __half22float2(*(__half2*)&sv.y);
        float4 acc = make_float4(f0.x, f0.y, f1.x, f1.y);  // self: h2[c]

        int j = 0;
        for (; j + 2 <= cnt; j += 2) {
            int s0 = g_bsrc[start + j];
            int s1 = g_bsrc[start + j + 1];
            uint2 a = ((const uint2*)(g_h2 + (size_t)s0 * HID))[lane];
            uint2 b = ((const uint2*)(g_h2 + (size_t)s1 * HID))[lane];
            float2 a0 = __half22float2(*(__half2*)&a.x);
            float2 a1 = __half22float2(*(__half2*)&a.y);
            float2 b0 = __half22float2(*(__half2*)&b.x);
            float2 b1 = __half22float2(*(__half2*)&b.y);
            acc.x += a0.x + b0.x;
            acc.y += a0.y + b0.y;
            acc.z += a1.x + b1.x;
            acc.w += a1.y + b1.y;
        }
        if (j < cnt) {
            int s0 = g_bsrc[start + j];
            uint2 a = ((const uint2*)(g_h2 + (size_t)s0 * HID))[lane];
            float2 a0 = __half22float2(*(__half2*)&a.x);
            float2 a1 = __half22float2(*(__half2*)&a.y);
            acc.x += a0.x; acc.y += a0.y;
            acc.z += a1.x; acc.w += a1.y;
        }

        float4 agg4 = make_float4(dd * acc.x, dd * acc.y, dd * acc.z, dd * acc.w);
        __half2 p0 = __floats2half2_rn(agg4.x, agg4.y);
        __half2 p1 = __floats2half2_rn(agg4.z, agg4.w);
        ((uint2*)(g_agg2 + (size_t)node * HID))[lane] =
            make_uint2(*(uint32_t*)&p0, *(uint32_t*)&p1);

        csum.x += agg4.x; csum.y += agg4.y; csum.z += agg4.z; csum.w += agg4.w;
        csq.x += agg4.x * agg4.x; csq.y += agg4.y * agg4.y;
        csq.z += agg4.z * agg4.z; csq.w += agg4.w * agg4.w;
    }

    atomicAdd(&bsum[lane * 4 + 0], csum.x);
    atomicAdd(&bsum[lane * 4 + 1], csum.y);
    atomicAdd(&bsum[lane * 4 + 2], csum.z);
    atomicAdd(&bsum[lane * 4 + 3], csum.w);
    atomicAdd(&bsq[lane * 4 + 0], csq.x);
    atomicAdd(&bsq[lane * 4 + 1], csq.y);
    atomicAdd(&bsq[lane * 4 + 2], csq.z);
    atomicAdd(&bsq[lane * 4 + 3], csq.w);
    __syncthreads();
    if (t < HID) {
        atomicAdd(&g_colsum[t], bsum[t]);
        atomicAdd(&g_colsq[t], bsq[t]);
    }
}

// 6) out = scale[c]*agg + shift[c]; BN coefficients per block; resets g_total.
__global__ void __launch_bounds__(256)
kk_out(float* __restrict__ out, const float* __restrict__ gamma,
       const float* __restrict__ beta, float inv_n, int n) {
    __shared__ float ssc[HID], ssh[HID];
    int t = threadIdx.x;
    if (blockIdx.x == 0 && t == 0) g_total = 0;   // state reset for next call
    if (t < HID) {
        float mean = g_colsum[t] * inv_n;
        float var = g_colsq[t] * inv_n - mean * mean;
        float sc = gamma[t] * rsqrtf(var + 1e-5f);
        ssc[t] = sc;
        ssh[t] = beta[t] - sc * mean;
    }
    __syncthreads();

    size_t total = (size_t)n * 32;   // groups of 4 cols
    for (size_t i = (size_t)blockIdx.x * blockDim.x + t; i < total;
         i += (size_t)gridDim.x * blockDim.x) {
        int c4 = (int)(i & 31);
        uint2 a = ((const uint2*)g_agg2)[i];
        float2 a0 = __half22float2(*(__half2*)&a.x);
        float2 a1 = __half22float2(*(__half2*)&a.y);
        float4 sc = *(const float4*)&ssc[c4 * 4];
        float4 sh = *(const float4*)&ssh[c4 * 4];
        float4 v;
        v.x = fmaf(a0.x, sc.x, sh.x);
        v.y = fmaf(a0.y, sc.y, sh.y);
        v.z = fmaf(a1.x, sc.z, sh.z);
        v.w = fmaf(a1.y, sc.w, sh.w);
        ((float4*)out)[i] = v;
    }
}

// ---------------------------------------------------------------------------
extern "C" void kernel_launch(void* const* d_in, const int* in_sizes, int n_in,
                              void* d_out, int out_size) {
    const float* x = (const float*)d_in[0];
    const int* ei = (const int*)d_in[1];          // int32 (JAX x64 disabled)
    const float* W = (const float*)d_in[2];
    const float* gamma = (const float*)d_in[4];
    const float* beta = (const float*)d_in[5];
    float* out = (float*)d_out;

    int n = in_sizes[0] / HID;
    int e = in_sizes[1] / 2;
    const int* erow = ei;
    const int* ecol = ei + e;

    int nb = (n + SCAN_BS - 1) / SCAN_BS;

    kk_deg<<<(e + 255) / 256, 256>>>(ecol, e);
    kk_allocscan<<<nb, SCAN_BS>>>(n);
    kk_scatter<<<(e + 255) / 256, 256>>>(erow, ecol, e);

    {
        cudaFuncSetAttribute(kk_gemm, cudaFuncAttributeMaxDynamicSharedMemorySize,
                             SM_TOT);
        int need = (n + 31) / 32;
        int blocks = need < 444 ? need : 444;  // persistent, 3 CTAs/SM
        kk_gemm<<<blocks, 128, SM_TOT>>>(x, W, n);
    }

    kk_aggstats<<<1184, 256>>>(n);
    kk_out<<<2048, 256>>>(out, gamma, beta, 1.0f / (float)n, n);
}